// round 12
// baseline (speedup 1.0000x reference)
#include <cuda_runtime.h>
#include <cuda_fp16.h>
#include <cuda_bf16.h>
#include <cstdint>

// GCN sparse aggregation: out[r,:] += vals[e] * embeds[cols[e],:]
// N=100000 nodes, E=1600000 edges, D=64, fp32 out.
//
// Round 11: 4-launch pipeline.
//   1) rank_conv : rank[e]=atomicAdd(count[rows[e]],1) FUSED with the
//                  fp32->half2 embed-table conversion (DRAM streaming work
//                  fills the ATOMG latency shadow; kills a whole kernel).
//   2) scan      : single-kernel decoupled-lookback exclusive scan of counts
//                  -> rowstart; resets count (replay invariant). Flag+value
//                  packed in one 64-bit relaxed word; warp-windowed lookback.
//   3) placeB    : g_edge[rowstart[r]+rank[e]]={col,val}; atomic-free; .cs on
//                  all its (last-touch) loads; also resets the scan descriptors.
//   4) aggregate : warp per node, lane owns one half2 of D=64, unroll-4,
//                  fp32 accumulation, .cs float2 store.
// Cache policy: .cs ONLY on last-touch streams. Hot L2 set: half2 table
// 12.8MB + packed edges 12.8MB + count/rowstart ~1MB.

#define D_FEAT 64
#define NV 100000
#define NE 1600000
#define SCAN_BS 512
#define NB ((NV + SCAN_BS - 1) / SCAN_BS)   // 196

__device__ int     g_count[NV];        // zero at load; scan restores 0
__device__ int     g_rowstart[NV + 1];
__device__ int     g_rank[NE];
__device__ int2    g_edge[NE];         // {col, val_bits}, grouped by row
__device__ __half2 g_embeds_h[(size_t)NV * 32];        // 12.8MB half2 table
__device__ unsigned long long g_desc[NB];              // lookback {flag,value}

// ---- memory helpers ----
__device__ __forceinline__ int4 ldcs_int4(const int4* p) {
    int4 v;
    asm volatile("ld.global.cs.v4.s32 {%0,%1,%2,%3}, [%4];"
                 : "=r"(v.x), "=r"(v.y), "=r"(v.z), "=r"(v.w) : "l"(p));
    return v;
}
__device__ __forceinline__ float4 ldcs_float4(const float4* p) {
    float4 v;
    asm volatile("ld.global.cs.v4.f32 {%0,%1,%2,%3}, [%4];"
                 : "=f"(v.x), "=f"(v.y), "=f"(v.z), "=f"(v.w) : "l"(p));
    return v;
}
__device__ __forceinline__ void stcs_float2(float2* p, float2 v) {
    asm volatile("st.global.cs.v2.f32 [%0], {%1,%2};"
                 :: "l"(p), "f"(v.x), "f"(v.y) : "memory");
}
__device__ __forceinline__ void st_rel_u64(unsigned long long* p, unsigned long long v) {
    asm volatile("st.relaxed.gpu.global.u64 [%0], %1;" :: "l"(p), "l"(v) : "memory");
}
__device__ __forceinline__ unsigned long long ld_rel_u64(const unsigned long long* p) {
    unsigned long long v;
    asm volatile("ld.relaxed.gpu.global.u64 %0, [%1];" : "=l"(v) : "l"(p) : "memory");
    return v;
}

// ---- 1) rank + embed conversion (fused) ----
__global__ void __launch_bounds__(256) rank_conv_kernel(
    const int4*   __restrict__ rows4,
    const float4* __restrict__ embeds4,
    int n_quads, int n_f4)
{
    int t      = blockIdx.x * blockDim.x + threadIdx.x;
    int stride = gridDim.x * blockDim.x;
    bool active = (t < n_quads);

    int4 r;
    int k0 = 0, k1 = 0, k2 = 0, k3 = 0;
    if (active) {
        r = __ldg(&rows4[t]);                 // default policy: placeB re-reads rows
        k0 = atomicAdd(&g_count[r.x], 1);     // 4 ATOMGs in flight
        k1 = atomicAdd(&g_count[r.y], 1);
        k2 = atomicAdd(&g_count[r.z], 1);
        k3 = atomicAdd(&g_count[r.w], 1);
    }

    // Convert a slice of the embed table while the atomics are in flight.
    for (int j = t; j < n_f4; j += stride) {
        float4 f = ldcs_float4(&embeds4[j]);  // last touch of fp32 embeds
        __half2 h0 = __floats2half2_rn(f.x, f.y);
        __half2 h1 = __floats2half2_rn(f.z, f.w);
        uint2 pk;
        pk.x = *reinterpret_cast<unsigned int*>(&h0);
        pk.y = *reinterpret_cast<unsigned int*>(&h1);
        *reinterpret_cast<uint2*>(&g_embeds_h[(size_t)j * 2]) = pk;   // hot
    }

    if (active)
        *reinterpret_cast<int4*>(&g_rank[t * 4]) = make_int4(k0, k1, k2, k3); // hot
}

__global__ void __launch_bounds__(256) rank_tail_kernel(
    const int* __restrict__ rows, int start, int n_edges)
{
    int e = start + blockIdx.x * blockDim.x + threadIdx.x;
    if (e < n_edges) g_rank[e] = atomicAdd(&g_count[rows[e]], 1);
}

// ---- 2) single-pass decoupled-lookback exclusive scan ----
__global__ void __launch_bounds__(SCAN_BS) scan_kernel(int n_nodes, int n_edges) {
    __shared__ int warp_sums[16];
    __shared__ int s_excl;
    int b    = blockIdx.x;
    int tid  = threadIdx.x;
    int lane = tid & 31;
    int wid  = tid >> 5;
    int g    = b * SCAN_BS + tid;

    int v = 0;
    if (g < n_nodes) {
        v = g_count[g];
        g_count[g] = 0;                      // invariant for next replay
    }

    // warp inclusive scan
    int incl = v;
    #pragma unroll
    for (int o = 1; o < 32; o <<= 1) {
        int n = __shfl_up_sync(0xffffffffu, incl, o);
        if (lane >= o) incl += n;
    }
    if (lane == 31) warp_sums[wid] = incl;
    __syncthreads();

    if (wid == 0) {
        int ws = (lane < 16) ? warp_sums[lane] : 0;
        #pragma unroll
        for (int o = 1; o < 32; o <<= 1) {
            int n = __shfl_up_sync(0xffffffffu, ws, o);
            if (lane >= o) ws += n;
        }
        if (lane < 16) warp_sums[lane] = ws;
    }
    __syncthreads();

    int block_total = warp_sums[15];
    int thread_excl = ((wid == 0) ? 0 : warp_sums[wid - 1]) + incl - v;

    if (wid == 0) {
        int sum = 0;
        if (b == 0) {
            if (lane == 0)
                st_rel_u64(&g_desc[0], (2ULL << 32) | (unsigned)block_total);
        } else {
            if (lane == 0)  // publish aggregate to unblock successors
                st_rel_u64(&g_desc[b], (1ULL << 32) | (unsigned)block_total);
            // warp-windowed lookback
            int base = b;
            bool done = false;
            while (!done) {
                int idx = base - 32 + lane;
                unsigned f = 1;
                int val = 0;
                if (idx >= 0) {
                    unsigned long long dd;
                    do {
                        dd = ld_rel_u64(&g_desc[idx]);
                        f = (unsigned)(dd >> 32);
                    } while (f == 0);
                    val = (int)(unsigned)dd;
                }
                unsigned m2 = __ballot_sync(0xffffffffu, f == 2u);
                int P = m2 ? (31 - __clz(m2)) : -1;
                if (P >= 0 && lane < P) val = 0;
                #pragma unroll
                for (int o = 16; o; o >>= 1)
                    val += __shfl_xor_sync(0xffffffffu, val, o);
                sum += val;
                if (P >= 0) done = true; else base -= 32;
            }
            if (lane == 0)
                st_rel_u64(&g_desc[b], (2ULL << 32) | (unsigned)(sum + block_total));
        }
        if (lane == 0) s_excl = sum;
    }
    __syncthreads();

    int excl = s_excl;
    if (g < n_nodes) g_rowstart[g] = excl + thread_excl;
    if (b == 0 && tid == 0) g_rowstart[n_nodes] = n_edges;
}

// ---- 3) placeB: atomic-free scatter into CSR slots (+ desc reset) ----
__global__ void __launch_bounds__(256) placeB_kernel(
    const int4*   __restrict__ rows4,
    const int4*   __restrict__ cols4,
    const float4* __restrict__ vals4,
    int n_quads)
{
    int t = blockIdx.x * blockDim.x + threadIdx.x;
    if (t < NB) g_desc[t] = 0;               // reset lookback state for next replay
    if (t >= n_quads) return;

    int4   r = ldcs_int4(&rows4[t]);         // last touch
    int4   c = ldcs_int4(&cols4[t]);         // last touch
    float4 v = ldcs_float4(&vals4[t]);       // last touch
    int4   k = ldcs_int4(reinterpret_cast<const int4*>(&g_rank[t * 4])); // last touch

    int s0 = __ldg(&g_rowstart[r.x]);
    int s1 = __ldg(&g_rowstart[r.y]);
    int s2 = __ldg(&g_rowstart[r.z]);
    int s3 = __ldg(&g_rowstart[r.w]);

    g_edge[s0 + k.x] = make_int2(c.x, __float_as_int(v.x));   // hot
    g_edge[s1 + k.y] = make_int2(c.y, __float_as_int(v.y));
    g_edge[s2 + k.z] = make_int2(c.z, __float_as_int(v.z));
    g_edge[s3 + k.w] = make_int2(c.w, __float_as_int(v.w));
}

__global__ void __launch_bounds__(256) placeB_tail_kernel(
    const int*   __restrict__ rows,
    const int*   __restrict__ cols,
    const float* __restrict__ vals,
    int start, int n_edges)
{
    int e = start + blockIdx.x * blockDim.x + threadIdx.x;
    if (e >= n_edges) return;
    int r = rows[e];
    int pos = __ldg(&g_rowstart[r]) + g_rank[e];
    g_edge[pos] = make_int2(cols[e], __float_as_int(vals[e]));
}

// ---- 4) aggregate: warp per node, fp16 gather, fp32 accumulate ----
__global__ void __launch_bounds__(256) aggregate_kernel(
    float2* __restrict__ out2, int n_nodes)
{
    int w    = (blockIdx.x * blockDim.x + threadIdx.x) >> 5;
    int lane = threadIdx.x & 31;
    if (w >= n_nodes) return;

    int i   = g_rowstart[w];
    int end = g_rowstart[w + 1];

    float ax = 0.f, ay = 0.f;

    for (; i + 3 < end; i += 4) {
        int2 p0 = __ldg(&g_edge[i]);
        int2 p1 = __ldg(&g_edge[i + 1]);
        int2 p2 = __ldg(&g_edge[i + 2]);
        int2 p3 = __ldg(&g_edge[i + 3]);
        float2 x0 = __half22float2(g_embeds_h[(size_t)p0.x * 32 + lane]);
        float2 x1 = __half22float2(g_embeds_h[(size_t)p1.x * 32 + lane]);
        float2 x2 = __half22float2(g_embeds_h[(size_t)p2.x * 32 + lane]);
        float2 x3 = __half22float2(g_embeds_h[(size_t)p3.x * 32 + lane]);
        float v0 = __int_as_float(p0.y);
        float v1 = __int_as_float(p1.y);
        float v2 = __int_as_float(p2.y);
        float v3 = __int_as_float(p3.y);
        ax += v0 * x0.x; ay += v0 * x0.y;
        ax += v1 * x1.x; ay += v1 * x1.y;
        ax += v2 * x2.x; ay += v2 * x2.y;
        ax += v3 * x3.x; ay += v3 * x3.y;
    }
    for (; i < end; ++i) {
        int2 p = __ldg(&g_edge[i]);
        float v = __int_as_float(p.y);
        float2 x = __half22float2(g_embeds_h[(size_t)p.x * 32 + lane]);
        ax += v * x.x; ay += v * x.y;
    }
    stcs_float2(&out2[(size_t)w * 32 + lane], make_float2(ax, ay));
}

extern "C" void kernel_launch(void* const* d_in, const int* in_sizes, int n_in,
                              void* d_out, int out_size)
{
    const int*   rows   = (const int*)d_in[0];
    const int*   cols   = (const int*)d_in[1];
    const float* vals   = (const float*)d_in[2];
    const float* embeds = (const float*)d_in[3];
    int n_edges = in_sizes[0];
    if (n_edges > NE) n_edges = NE;
    int n_nodes = out_size / D_FEAT;
    if (n_nodes > NV) n_nodes = NV;
    int n_f4 = in_sizes[3] / 4;

    float* out = (float*)d_out;

    int n_quads   = n_edges >> 2;
    int quad_tail = n_quads << 2;

    {   // 1) rank + convert (fused)
        int blocks = (n_quads + 255) / 256;
        rank_conv_kernel<<<blocks, 256>>>(
            (const int4*)rows, (const float4*)embeds, n_quads, n_f4);
        if (quad_tail < n_edges) {
            int tail = n_edges - quad_tail;
            rank_tail_kernel<<<(tail + 255) / 256, 256>>>(rows, quad_tail, n_edges);
        }
    }
    {   // 2) single-pass scan
        scan_kernel<<<NB, SCAN_BS>>>(n_nodes, n_edges);
    }
    {   // 3) placeB
        int blocks = (n_quads + 255) / 256;
        placeB_kernel<<<blocks, 256>>>(
            (const int4*)rows, (const int4*)cols, (const float4*)vals, n_quads);
        if (quad_tail < n_edges) {
            int tail = n_edges - quad_tail;
            placeB_tail_kernel<<<(tail + 255) / 256, 256>>>(
                rows, cols, vals, quad_tail, n_edges);
        }
    }
    {   // 4) aggregate
        long long total = (long long)n_nodes * 32;
        int blocks = (int)((total + 255) / 256);
        aggregate_kernel<<<blocks, 256>>>((float2*)out, n_nodes);
    }
}

// round 13
// speedup vs baseline: 1.1317x; 1.1317x over previous
#include <cuda_runtime.h>
#include <cuda_bf16.h>
#include <cstdint>

// GCN sparse aggregation: out[r,:] += vals[e] * embeds[cols[e],:]
// N=100000 nodes, E=1600000 edges, D=64, fp32.
//
// Round 12: fp32 CSR rank-fusion pipeline (round-8 skeleton = best @76.5us)
// with the two validated improvements and nothing speculative:
//   1) rank   : rank[e] = atomicAdd(count[rows[e]],1)   (hist+slot in one)
//   2) scan   : single-kernel decoupled-lookback exclusive scan (replaces
//               the two-kernel scan; validated in round 11)
//   3) placeB : g_edge[rowstart[r]+rank[e]] = {col,val}; atomic-free; .cs on
//               its last-touch loads; resets scan descriptors for next replay
//   4) aggregate: warp per node, lane owns a float2 of D=64, unroll-4, fp32
//               accumulation, .cs store (out is last touch).
// fp16 abandoned: three attempts never beat fp32 (aggregate measured SLOWER
// with fp16). The fp32 aggregate runs at the ~6300 B/cyc LTS cap — floor.

#define D_FEAT 64
#define NV 100000
#define NE 1600000
#define SCAN_BS 512
#define NB ((NV + SCAN_BS - 1) / SCAN_BS)   // 196

__device__ int  g_count[NV];        // zero at load; scan restores 0 each run
__device__ int  g_rowstart[NV + 1];
__device__ int  g_rank[NE];
__device__ int2 g_edge[NE];         // {col, val_bits}, grouped by row
__device__ unsigned long long g_desc[NB];   // lookback {flag,value}; placeB resets

// ---- memory helpers ----
__device__ __forceinline__ int4 ldcs_int4(const int4* p) {
    int4 v;
    asm volatile("ld.global.cs.v4.s32 {%0,%1,%2,%3}, [%4];"
                 : "=r"(v.x), "=r"(v.y), "=r"(v.z), "=r"(v.w) : "l"(p));
    return v;
}
__device__ __forceinline__ float4 ldcs_float4(const float4* p) {
    float4 v;
    asm volatile("ld.global.cs.v4.f32 {%0,%1,%2,%3}, [%4];"
                 : "=f"(v.x), "=f"(v.y), "=f"(v.z), "=f"(v.w) : "l"(p));
    return v;
}
__device__ __forceinline__ void stcs_float2(float2* p, float2 v) {
    asm volatile("st.global.cs.v2.f32 [%0], {%1,%2};"
                 :: "l"(p), "f"(v.x), "f"(v.y) : "memory");
}
__device__ __forceinline__ void st_rel_u64(unsigned long long* p, unsigned long long v) {
    asm volatile("st.relaxed.gpu.global.u64 [%0], %1;" :: "l"(p), "l"(v) : "memory");
}
__device__ __forceinline__ unsigned long long ld_rel_u64(const unsigned long long* p) {
    unsigned long long v;
    asm volatile("ld.relaxed.gpu.global.u64 %0, [%1];" : "=l"(v) : "l"(p) : "memory");
    return v;
}

// ---- 1) rank: histogram + slot assignment ----
__global__ void __launch_bounds__(256) rank_kernel(
    const int4* __restrict__ rows4, int n_quads)
{
    int t = blockIdx.x * blockDim.x + threadIdx.x;
    if (t >= n_quads) return;
    int4 r = __ldg(&rows4[t]);               // default: placeB re-reads rows
    int k0 = atomicAdd(&g_count[r.x], 1);
    int k1 = atomicAdd(&g_count[r.y], 1);
    int k2 = atomicAdd(&g_count[r.z], 1);
    int k3 = atomicAdd(&g_count[r.w], 1);
    *reinterpret_cast<int4*>(&g_rank[t * 4]) = make_int4(k0, k1, k2, k3);  // hot
}

__global__ void __launch_bounds__(256) rank_tail_kernel(
    const int* __restrict__ rows, int start, int n_edges)
{
    int e = start + blockIdx.x * blockDim.x + threadIdx.x;
    if (e < n_edges) g_rank[e] = atomicAdd(&g_count[rows[e]], 1);
}

// ---- 2) single-pass decoupled-lookback exclusive scan ----
__global__ void __launch_bounds__(SCAN_BS) scan_kernel(int n_nodes, int n_edges) {
    __shared__ int warp_sums[16];
    __shared__ int s_excl;
    int b    = blockIdx.x;
    int tid  = threadIdx.x;
    int lane = tid & 31;
    int wid  = tid >> 5;
    int g    = b * SCAN_BS + tid;

    int v = 0;
    if (g < n_nodes) {
        v = g_count[g];
        g_count[g] = 0;                      // invariant for next replay
    }

    int incl = v;
    #pragma unroll
    for (int o = 1; o < 32; o <<= 1) {
        int n = __shfl_up_sync(0xffffffffu, incl, o);
        if (lane >= o) incl += n;
    }
    if (lane == 31) warp_sums[wid] = incl;
    __syncthreads();

    if (wid == 0) {
        int ws = (lane < 16) ? warp_sums[lane] : 0;
        #pragma unroll
        for (int o = 1; o < 32; o <<= 1) {
            int n = __shfl_up_sync(0xffffffffu, ws, o);
            if (lane >= o) ws += n;
        }
        if (lane < 16) warp_sums[lane] = ws;
    }
    __syncthreads();

    int block_total = warp_sums[15];
    int thread_excl = ((wid == 0) ? 0 : warp_sums[wid - 1]) + incl - v;

    if (wid == 0) {
        int sum = 0;
        if (b == 0) {
            if (lane == 0)
                st_rel_u64(&g_desc[0], (2ULL << 32) | (unsigned)block_total);
        } else {
            if (lane == 0)
                st_rel_u64(&g_desc[b], (1ULL << 32) | (unsigned)block_total);
            int base = b;
            bool done = false;
            while (!done) {
                int idx = base - 32 + lane;
                unsigned f = 1;
                int val = 0;
                if (idx >= 0) {
                    unsigned long long dd;
                    do {
                        dd = ld_rel_u64(&g_desc[idx]);
                        f = (unsigned)(dd >> 32);
                    } while (f == 0);
                    val = (int)(unsigned)dd;
                }
                unsigned m2 = __ballot_sync(0xffffffffu, f == 2u);
                int P = m2 ? (31 - __clz(m2)) : -1;
                if (P >= 0 && lane < P) val = 0;
                #pragma unroll
                for (int o = 16; o; o >>= 1)
                    val += __shfl_xor_sync(0xffffffffu, val, o);
                sum += val;
                if (P >= 0) done = true; else base -= 32;
            }
            if (lane == 0)
                st_rel_u64(&g_desc[b], (2ULL << 32) | (unsigned)(sum + block_total));
        }
        if (lane == 0) s_excl = sum;
    }
    __syncthreads();

    int excl = s_excl;
    if (g < n_nodes) g_rowstart[g] = excl + thread_excl;
    if (b == 0 && tid == 0) g_rowstart[n_nodes] = n_edges;
}

// ---- 3) placeB: atomic-free scatter into CSR slots (+ desc reset) ----
__global__ void __launch_bounds__(256) placeB_kernel(
    const int4*   __restrict__ rows4,
    const int4*   __restrict__ cols4,
    const float4* __restrict__ vals4,
    int n_quads)
{
    int t = blockIdx.x * blockDim.x + threadIdx.x;
    if (t < NB) g_desc[t] = 0;               // reset lookback state for next replay
    if (t >= n_quads) return;

    int4   r = ldcs_int4(&rows4[t]);         // last touch
    int4   c = ldcs_int4(&cols4[t]);         // last touch
    float4 v = ldcs_float4(&vals4[t]);       // last touch
    int4   k = ldcs_int4(reinterpret_cast<const int4*>(&g_rank[t * 4]));  // last touch

    int s0 = __ldg(&g_rowstart[r.x]);
    int s1 = __ldg(&g_rowstart[r.y]);
    int s2 = __ldg(&g_rowstart[r.z]);
    int s3 = __ldg(&g_rowstart[r.w]);

    g_edge[s0 + k.x] = make_int2(c.x, __float_as_int(v.x));   // hot
    g_edge[s1 + k.y] = make_int2(c.y, __float_as_int(v.y));
    g_edge[s2 + k.z] = make_int2(c.z, __float_as_int(v.z));
    g_edge[s3 + k.w] = make_int2(c.w, __float_as_int(v.w));
}

__global__ void __launch_bounds__(256) placeB_tail_kernel(
    const int*   __restrict__ rows,
    const int*   __restrict__ cols,
    const float* __restrict__ vals,
    int start, int n_edges)
{
    int e = start + blockIdx.x * blockDim.x + threadIdx.x;
    if (e >= n_edges) return;
    int r = rows[e];
    int pos = __ldg(&g_rowstart[r]) + g_rank[e];
    g_edge[pos] = make_int2(cols[e], __float_as_int(vals[e]));
}

// ---- 4) aggregate: warp per node, fp32 gather, fp32 accumulate ----
__global__ void __launch_bounds__(256) aggregate_kernel(
    const float2* __restrict__ embeds2,   // [NV, 32] float2
    float2*       __restrict__ out2,      // [NV, 32] float2
    int n_nodes)
{
    int w    = (blockIdx.x * blockDim.x + threadIdx.x) >> 5;
    int lane = threadIdx.x & 31;
    if (w >= n_nodes) return;

    int i   = g_rowstart[w];
    int end = g_rowstart[w + 1];

    float ax = 0.f, ay = 0.f;

    for (; i + 3 < end; i += 4) {
        int2 p0 = __ldg(&g_edge[i]);
        int2 p1 = __ldg(&g_edge[i + 1]);
        int2 p2 = __ldg(&g_edge[i + 2]);
        int2 p3 = __ldg(&g_edge[i + 3]);
        float2 x0 = __ldg(&embeds2[(size_t)p0.x * 32 + lane]);
        float2 x1 = __ldg(&embeds2[(size_t)p1.x * 32 + lane]);
        float2 x2 = __ldg(&embeds2[(size_t)p2.x * 32 + lane]);
        float2 x3 = __ldg(&embeds2[(size_t)p3.x * 32 + lane]);
        float v0 = __int_as_float(p0.y);
        float v1 = __int_as_float(p1.y);
        float v2 = __int_as_float(p2.y);
        float v3 = __int_as_float(p3.y);
        ax += v0 * x0.x; ay += v0 * x0.y;
        ax += v1 * x1.x; ay += v1 * x1.y;
        ax += v2 * x2.x; ay += v2 * x2.y;
        ax += v3 * x3.x; ay += v3 * x3.y;
    }
    for (; i < end; ++i) {
        int2 p = __ldg(&g_edge[i]);
        float v = __int_as_float(p.y);
        float2 x = __ldg(&embeds2[(size_t)p.x * 32 + lane]);
        ax += v * x.x; ay += v * x.y;
    }
    stcs_float2(&out2[(size_t)w * 32 + lane], make_float2(ax, ay));  // last touch
}

extern "C" void kernel_launch(void* const* d_in, const int* in_sizes, int n_in,
                              void* d_out, int out_size)
{
    const int*   rows   = (const int*)d_in[0];
    const int*   cols   = (const int*)d_in[1];
    const float* vals   = (const float*)d_in[2];
    const float* embeds = (const float*)d_in[3];
    int n_edges = in_sizes[0];
    if (n_edges > NE) n_edges = NE;
    int n_nodes = out_size / D_FEAT;
    if (n_nodes > NV) n_nodes = NV;

    float* out = (float*)d_out;

    int n_quads   = n_edges >> 2;
    int quad_tail = n_quads << 2;

    {   // 1) rank
        int blocks = (n_quads + 255) / 256;
        rank_kernel<<<blocks, 256>>>((const int4*)rows, n_quads);
        if (quad_tail < n_edges) {
            int tail = n_edges - quad_tail;
            rank_tail_kernel<<<(tail + 255) / 256, 256>>>(rows, quad_tail, n_edges);
        }
    }
    {   // 2) single-pass scan
        scan_kernel<<<NB, SCAN_BS>>>(n_nodes, n_edges);
    }
    {   // 3) placeB
        int blocks = (n_quads + 255) / 256;
        placeB_kernel<<<blocks, 256>>>(
            (const int4*)rows, (const int4*)cols, (const float4*)vals, n_quads);
        if (quad_tail < n_edges) {
            int tail = n_edges - quad_tail;
            placeB_tail_kernel<<<(tail + 255) / 256, 256>>>(
                rows, cols, vals, quad_tail, n_edges);
        }
    }
    {   // 4) aggregate
        long long total = (long long)n_nodes * 32;
        int blocks = (int)((total + 255) / 256);
        aggregate_kernel<<<blocks, 256>>>(
            (const float2*)embeds, (float2*)out, n_nodes);
    }
}